// round 13
// baseline (speedup 1.0000x reference)
#include <cuda_runtime.h>
#include <cuda_fp16.h>
#include <math.h>
#include <stdint.h>

#define TOK 4096        // B*S
#define Hd  1024
#define Id  4096
#define NHh 16
#define DHh 64

// ---------------- scratch (device globals; no allocs) ----------------
__device__ float g_xs [TOK * Hd];
__device__ float g_att[TOK * Hd];
__device__ float g_tmp[TOK * Hd];
__device__ float g_mask2[TOK];          // mask * log2(e)

// fp16 activation buffers
__device__ __half g_xh[TOK * Hd];
__device__ __half g_yh[TOK * Hd];
__device__ __half g_qh[TOK * Hd];
__device__ __half g_kh[TOK * Hd];
__device__ __half g_vh[TOK * Hd];
__device__ __half g_ch[TOK * Hd];
__device__ __half g_ah[TOK * Hd];
__device__ __half g_ih[TOK * Id];

// transposed fp16 weights [N, K]
__device__ __half g_wq[Hd * Hd];
__device__ __half g_wk[Hd * Hd];
__device__ __half g_wv[Hd * Hd];
__device__ __half g_wo[Hd * Hd];
__device__ __half g_wi[Id * Hd];
__device__ __half g_w2[Hd * Id];

// ---------------- helpers ----------------
__device__ __forceinline__ uint32_t smem_u32(const void* p) {
  uint32_t a;
  asm("{ .reg .u64 t; cvta.to.shared.u64 t, %1; cvt.u32.u64 %0, t; }" : "=r"(a) : "l"(p));
  return a;
}
__device__ __forceinline__ void cp_async16(uint32_t dst, const void* src) {
  asm volatile("cp.async.cg.shared.global [%0], [%1], 16;" :: "r"(dst), "l"(src) : "memory");
}
#define CP_COMMIT() asm volatile("cp.async.commit_group;" ::: "memory")
#define CP_WAIT(n)  asm volatile("cp.async.wait_group %0;" :: "n"(n) : "memory")

__device__ __forceinline__ void ldsm4(uint32_t* r, uint32_t addr) {
  asm volatile("ldmatrix.sync.aligned.m8n8.x4.shared.b16 {%0,%1,%2,%3}, [%4];"
               : "=r"(r[0]), "=r"(r[1]), "=r"(r[2]), "=r"(r[3]) : "r"(addr));
}
__device__ __forceinline__ void ldsm4t(uint32_t* r, uint32_t addr) {
  asm volatile("ldmatrix.sync.aligned.m8n8.x4.trans.shared.b16 {%0,%1,%2,%3}, [%4];"
               : "=r"(r[0]), "=r"(r[1]), "=r"(r[2]), "=r"(r[3]) : "r"(addr));
}
__device__ __forceinline__ void mma16816(float* d, const uint32_t* a, const uint32_t* b) {
  asm volatile("mma.sync.aligned.m16n8k16.row.col.f32.f16.f16.f32 "
               "{%0,%1,%2,%3}, {%4,%5,%6,%7}, {%8,%9}, {%0,%1,%2,%3};"
               : "+f"(d[0]), "+f"(d[1]), "+f"(d[2]), "+f"(d[3])
               : "r"(a[0]), "r"(a[1]), "r"(a[2]), "r"(a[3]), "r"(b[0]), "r"(b[1]));
}
__device__ __forceinline__ uint32_t packh(float a, float b) {
  __half2 t = __floats2half2_rn(a, b);
  return *(uint32_t*)&t;
}

__device__ __forceinline__ uint32_t swz128(int row, int c16) {
  return (uint32_t)(row * 128 + ((c16 ^ (row & 7)) << 4));
}

// ---------------- fused prologue: routing (blocks 0..TOK-1) + weight cvt ----------------
struct CvtJobs {
  const float* W[6];
  __half* T[6];
  int K[6], N[6], tilesX[6], start[6];  // start[] offset AFTER routing blocks
};

__global__ void __launch_bounds__(256) prologue_kernel(
    const float* __restrict__ x, const float* __restrict__ y,
    const float* __restrict__ mask, const int* __restrict__ tptr,
    float* __restrict__ xs, float* __restrict__ mask2,
    __half* __restrict__ xh, __half* __restrict__ yh,
    CvtJobs jb) {
  const int blk = blockIdx.x;
  const int tid = threadIdx.x;

  if (blk >= TOK) {
    const int b = blk - TOK;
    int j = 0;
    #pragma unroll
    for (int i = 1; i < 6; i++) if (b >= jb.start[i]) j = i;
    const int local = b - jb.start[j];
    const int K = jb.K[j], N = jb.N[j];
    const int nb = (local % jb.tilesX[j]) * 32;
    const int kb = (local / jb.tilesX[j]) * 32;
    const float* W = jb.W[j];
    __half* T = jb.T[j];

    __shared__ float t[32][33];
    const int tx = tid & 31, ty = tid >> 5;
    #pragma unroll
    for (int i = 0; i < 32; i += 8)
      t[ty + i][tx] = W[(size_t)(kb + ty + i) * N + nb + tx];
    __syncthreads();
    #pragma unroll
    for (int i = 0; i < 32; i += 8)
      T[(size_t)(nb + ty + i) * K + kb + tx] = __float2half_rn(t[tx][ty + i]);
    return;
  }

  const int token = blk;
  const long base = (long)token * Hd;
  if (tid == 32) mask2[token] = mask[token] * 1.4426950408889634f;
  float sxx = 0.f, sxy = 0.f, syy = 0.f;
  for (int i = tid; i < Hd; i += 256) {
    float a = x[base + i], bb = y[base + i];
    sxx += a * a; sxy += a * bb; syy += bb * bb;
  }
  #pragma unroll
  for (int o = 16; o; o >>= 1) {
    sxx += __shfl_xor_sync(0xffffffffu, sxx, o);
    sxy += __shfl_xor_sync(0xffffffffu, sxy, o);
    syy += __shfl_xor_sync(0xffffffffu, syy, o);
  }
  __shared__ float red[8][3];
  __shared__ float sc[2];
  if ((tid & 31) == 0) { red[tid >> 5][0] = sxx; red[tid >> 5][1] = sxy; red[tid >> 5][2] = syy; }
  __syncthreads();
  if (tid == 0) {
    float a = 0.f, bb = 0.f, c = 0.f;
    #pragma unroll
    for (int i = 0; i < 8; i++) { a += red[i][0]; bb += red[i][1]; c += red[i][2]; }
    const int t = *tptr;
    float b1 = 0.f, b2 = 0.f, c1 = 0.5f, c2 = 0.5f;
    for (int it = 0; it < t; it++) {
      if (it > 0) {
        float mm = fmaxf(b1, b2);
        float e1 = expf(b1 - mm), e2 = expf(b2 - mm);
        float inv = 1.0f / (e1 + e2);
        c1 = e1 * inv; c2 = e2 * inv;
      }
      float vv = c1 * c1 * a + 2.0f * c1 * c2 * bb + c2 * c2 * c;
      float n  = sqrtf(vv);
      float f  = n / (1.0f + vv);
      b1 += f * (c1 * a  + c2 * bb);
      b2 += f * (c1 * bb + c2 * c );
    }
    sc[0] = c1; sc[1] = c2;
  }
  __syncthreads();
  const float c1 = sc[0], c2 = sc[1];
  for (int i = tid; i < Hd; i += 256) {
    const float vx = c1 * x[base + i];
    const float vy = c2 * y[base + i];
    xs[base + i] = vx;
    xh[base + i] = __float2half_rn(vx);
    yh[base + i] = __float2half_rn(vy);
  }
}

// ---------------- HMMA GEMM (R9 winner config, frozen) ----------------
struct GemmJob {
  const __half *A, *B;
  const float* bias;
  float* C;
  __half* Ch;
  float oscale;
  int outmode;   // 0: fp32 C; 2: fp16 Ch
  int gelu;
};

__global__ void __launch_bounds__(256, 2)
gemm_mma_kernel(GemmJob j0, GemmJob j1, GemmJob j2, int M, int N, int K) {
  extern __shared__ __align__(128) char sm[];
  const uint32_t smb = smem_u32(sm);
  const GemmJob j = (blockIdx.z == 0) ? j0 : ((blockIdx.z == 1) ? j1 : j2);
  const int tid = threadIdx.x;
  const int wid = tid >> 5, lane = tid & 31;
  const int bm = blockIdx.y * 128, bn = blockIdx.x * 128;
  const int warp_m = wid & 1, warp_n = wid >> 1;
  const int NK = K >> 6;

  auto soA = [](int s) -> uint32_t { return (uint32_t)(s * 32768); };
  auto soB = [](int s) -> uint32_t { return (uint32_t)(s * 32768 + 16384); };

  auto load_stage = [&](int kt, int s) {
    const int koff = kt * 64;
    #pragma unroll
    for (int jj = 0; jj < 4; jj++) {
      const int ch = tid + jj * 256;
      const int row = ch >> 3, c = ch & 7;
      const uint32_t d = swz128(row, c);
      cp_async16(smb + soA(s) + d, j.A + (size_t)(bm + row) * K + koff + c * 8);
      cp_async16(smb + soB(s) + d, j.B + (size_t)(bn + row) * K + koff + c * 8);
    }
  };

  float acc[4][4][4];
  #pragma unroll
  for (int i = 0; i < 4; i++)
    #pragma unroll
    for (int jj = 0; jj < 4; jj++)
      #pragma unroll
      for (int q = 0; q < 4; q++) acc[i][jj][q] = 0.f;

  load_stage(0, 0); CP_COMMIT();
  load_stage(1, 1); CP_COMMIT();

  const int la_row = (lane & 7) + ((lane >> 3) & 1) * 8;
  const int la_c   = (lane >> 4);
  const int lb_row = (lane & 7) + (lane >> 4) * 8;
  const int lb_c   = (lane >> 3) & 1;

  int s = 0;
  for (int kt = 0; kt < NK; kt++) {
    if (kt + 1 < NK) { CP_WAIT(1); } else { CP_WAIT(0); }
    __syncthreads();
    if (kt + 2 < NK) { load_stage(kt + 2, (s + 2 > 2) ? s - 1 : s + 2); CP_COMMIT(); }

    const uint32_t baseA = smb + soA(s);
    const uint32_t baseB = smb + soB(s);

    #pragma unroll
    for (int ks = 0; ks < 4; ks++) {
      uint32_t a4[4][4], b4[2][4];
      #pragma unroll
      for (int tm = 0; tm < 4; tm++)
        ldsm4(a4[tm], baseA + swz128(warp_m * 64 + tm * 16 + la_row, ks * 2 + la_c));
      #pragma unroll
      for (int tn2 = 0; tn2 < 2; tn2++)
        ldsm4(b4[tn2], baseB + swz128(warp_n * 32 + tn2 * 16 + lb_row, ks * 2 + lb_c));
      #pragma unroll
      for (int tm = 0; tm < 4; tm++)
        #pragma unroll
        for (int tn = 0; tn < 4; tn++)
          mma16816(acc[tm][tn], a4[tm], &b4[tn >> 1][(tn & 1) * 2]);
    }
    s = (s == 2) ? 0 : s + 1;
  }

  const int g = lane >> 2, tq = lane & 3;
  #pragma unroll
  for (int tm = 0; tm < 4; tm++) {
    #pragma unroll
    for (int tn = 0; tn < 4; tn++) {
      const int col = bn + warp_n * 32 + tn * 8 + tq * 2;
      const float b0 = j.bias[col], b1 = j.bias[col + 1];
      #pragma unroll
      for (int half = 0; half < 2; half++) {
        const int row = bm + warp_m * 64 + tm * 16 + g + half * 8;
        float vx = (acc[tm][tn][half * 2 + 0] + b0) * j.oscale;
        float vy = (acc[tm][tn][half * 2 + 1] + b1) * j.oscale;
        if (j.gelu) {
          vx = 0.5f * vx * (1.0f + erff(vx * 0.7071067811865476f));
          vy = 0.5f * vy * (1.0f + erff(vy * 0.7071067811865476f));
        }
        if (j.outmode == 0) {
          float2 v; v.x = vx; v.y = vy;
          *(float2*)(j.C + (size_t)row * N + col) = v;
        } else {
          *(uint32_t*)(j.Ch + (size_t)row * N + col) = packh(vx, vy);
        }
      }
    }
  }
}

// ---------------- HMMA flash attention: 128-key KV tiles, 8 iterations ----------------
// smem: Q 8KB + 2 stages x (K 16KB + V 16KB) = 72KB. 2 CTAs/SM.
__global__ void __launch_bounds__(128, 2)
attn_mma_kernel(const __half* __restrict__ Qh,
                const __half* __restrict__ Kh, const __half* __restrict__ Vh,
                const float* __restrict__ mask2,
                __half* __restrict__ Ch) {
  extern __shared__ __align__(128) char sm[];
  const uint32_t smb = smem_u32(sm);
  const int tid = threadIdx.x;
  const int warp = tid >> 5, lane = tid & 31;
  const int qt = blockIdx.x, h = blockIdx.y, b = blockIdx.z;
  const int g = lane >> 2, tq = lane & 3;

  const int la_row = (lane & 7) + ((lane >> 3) & 1) * 8;
  const int la_c   = (lane >> 4);
  const int lb_row = (lane & 7) + (lane >> 4) * 8;
  const int lb_c   = (lane >> 3) & 1;
  const int lv_row = (lane & 7) + ((lane >> 3) & 1) * 8;
  const int lv_c   = (lane >> 4);

  // Q: 64 rows x 64 cols
  {
    #pragma unroll
    for (int jj = 0; jj < 4; jj++) {
      const int ch = tid + jj * 128;
      const int row = ch >> 3, c = ch & 7;
      cp_async16(smb + swz128(row, c),
                 Qh + (size_t)(b * 1024 + qt * 64 + row) * Hd + h * 64 + c * 8);
    }
  }
  // KV tile: 128 keys; K 16KB + V 16KB per stage
  auto load_kv = [&](int kt, int s) {
    const uint32_t so = smb + 8192 + s * 32768;
    #pragma unroll
    for (int jj = 0; jj < 8; jj++) {
      const int ch = tid + jj * 128;
      const int row = ch >> 3, c = ch & 7;
      const uint32_t d = swz128(row, c);
      const size_t gk = (size_t)(b * 1024 + kt * 128 + row) * Hd + h * 64 + c * 8;
      cp_async16(so + d,         Kh + gk);
      cp_async16(so + 16384 + d, Vh + gk);
    }
  };
  load_kv(0, 0);
  CP_COMMIT();

  float m0 = -1e30f, m1 = -1e30f, l0 = 0.f, l1 = 0.f;
  float oacc[8][4];
  #pragma unroll
  for (int jj = 0; jj < 8; jj++)
    #pragma unroll
    for (int q = 0; q < 4; q++) oacc[jj][q] = 0.f;

  for (int kt = 0; kt < 8; kt++) {
    const int s = kt & 1;
    if (kt + 1 < 8) { load_kv(kt + 1, 1 - s); CP_COMMIT(); CP_WAIT(1); }
    else            { CP_WAIT(0); }
    __syncthreads();

    const uint32_t sK = smb + 8192 + s * 32768;
    const uint32_t sV = sK + 16384;

    // ---- S = Q K^T (16 q rows x 128 keys per warp) ----
    float sacc[16][4];
    #pragma unroll
    for (int jj = 0; jj < 16; jj++)
      #pragma unroll
      for (int q = 0; q < 4; q++) sacc[jj][q] = 0.f;

    #pragma unroll
    for (int kc = 0; kc < 4; kc++) {
      uint32_t q4[4];
      ldsm4(q4, smb + swz128(warp * 16 + la_row, kc * 2 + la_c));
      #pragma unroll
      for (int n16 = 0; n16 < 8; n16++) {
        uint32_t k4[4];
        ldsm4(k4, sK + swz128(n16 * 16 + lb_row, kc * 2 + lb_c));
        mma16816(sacc[2 * n16],     q4, k4);
        mma16816(sacc[2 * n16 + 1], q4, k4 + 2);
      }
    }

    // ---- online softmax over 128 keys ----
    const float* mrow = mask2 + b * 1024 + kt * 128;
    float mx0 = -1e30f, mx1 = -1e30f;
    #pragma unroll
    for (int jj = 0; jj < 16; jj++) {
      const float2 mv = *(const float2*)(mrow + jj * 8 + 2 * tq);
      sacc[jj][0] += mv.x;
      sacc[jj][1] += mv.y;
      sacc[jj][2] += mv.x;
      sacc[jj][3] += mv.y;
      mx0 = fmaxf(mx0, fmaxf(sacc[jj][0], sacc[jj][1]));
      mx1 = fmaxf(mx1, fmaxf(sacc[jj][2], sacc[jj][3]));
    }
    mx0 = fmaxf(mx0, __shfl_xor_sync(0xffffffffu, mx0, 1));
    mx0 = fmaxf(mx0, __shfl_xor_sync(0xffffffffu, mx0, 2));
    mx1 = fmaxf(mx1, __shfl_xor_sync(0xffffffffu, mx1, 1));
    mx1 = fmaxf(mx1, __shfl_xor_sync(0xffffffffu, mx1, 2));
    const float mn0 = fmaxf(m0, mx0), mn1 = fmaxf(m1, mx1);
    const float rs0 = exp2f(m0 - mn0), rs1 = exp2f(m1 - mn1);
    m0 = mn0; m1 = mn1;

    float sum0 = 0.f, sum1 = 0.f;
    uint32_t ph01[16], ph23[16];
    #pragma unroll
    for (int jj = 0; jj < 16; jj++) {
      const float p0 = exp2f(sacc[jj][0] - mn0), p1 = exp2f(sacc[jj][1] - mn0);
      const float p2 = exp2f(sacc[jj][2] - mn1), p3 = exp2f(sacc[jj][3] - mn1);
      sum0 += p0 + p1; sum1 += p2 + p3;
      ph01[jj] = packh(p0, p1);
      ph23[jj] = packh(p2, p3);
    }
    #pragma unroll
    for (int jj = 0; jj < 8; jj++) {
      oacc[jj][0] *= rs0; oacc[jj][1] *= rs0;
      oacc[jj][2] *= rs1; oacc[jj][3] *= rs1;
    }
    sum0 += __shfl_xor_sync(0xffffffffu, sum0, 1);
    sum0 += __shfl_xor_sync(0xffffffffu, sum0, 2);
    sum1 += __shfl_xor_sync(0xffffffffu, sum1, 1);
    sum1 += __shfl_xor_sync(0xffffffffu, sum1, 2);
    l0 = l0 * rs0 + sum0;
    l1 = l1 * rs1 + sum1;

    // ---- O += P V (K-dim = 128 keys, 8 chunks of 16) ----
    #pragma unroll
    for (int kc = 0; kc < 8; kc++) {
      uint32_t ah[4] = {ph01[2*kc], ph23[2*kc], ph01[2*kc+1], ph23[2*kc+1]};
      #pragma unroll
      for (int n16 = 0; n16 < 4; n16++) {
        uint32_t v4[4];
        ldsm4t(v4, sV + swz128(kc * 16 + lv_row, n16 * 2 + lv_c));
        mma16816(oacc[2 * n16],     ah, v4);
        mma16816(oacc[2 * n16 + 1], ah, v4 + 2);
      }
    }
    __syncthreads();
  }

  const float inv0 = 1.f / l0, inv1 = 1.f / l1;
  const int row0 = b * 1024 + qt * 64 + warp * 16 + g;
  #pragma unroll
  for (int jj = 0; jj < 8; jj++) {
    const int col = h * 64 + (jj >> 1) * 16 + (jj & 1) * 8 + 2 * tq;
    *(uint32_t*)(Ch + (size_t)row0 * Hd + col)       = packh(oacc[jj][0] * inv0, oacc[jj][1] * inv0);
    *(uint32_t*)(Ch + (size_t)(row0 + 8) * Hd + col) = packh(oacc[jj][2] * inv1, oacc[jj][3] * inv1);
  }
}

// ---------------- fused residual + RMSNorm (float4 vectorized) ----------------
template<bool FOUT>
__global__ void __launch_bounds__(256) rms_kernel(
    const float* __restrict__ in, const float* __restrict__ res,
    const float* __restrict__ g, float* __restrict__ out,
    __half* __restrict__ oh) {
  const int row = blockIdx.x, tid = threadIdx.x;
  __shared__ float red[8];
  __shared__ float s_inv;
  const long base = (long)row * Hd;

  float4 v4 = *(const float4*)(in + base + tid * 4);
  const float4 r4 = *(const float4*)(res + base + tid * 4);
  v4.x += r4.x; v4.y += r4.y; v4.z += r4.z; v4.w += r4.w;
  float ss = v4.x * v4.x + v4.y * v4.y + v4.z * v4.z + v4.w * v4.w;

  #pragma unroll
  for (int o = 16; o; o >>= 1) ss += __shfl_xor_sync(0xffffffffu, ss, o);
  if ((tid & 31) == 0) red[tid >> 5] = ss;
  __syncthreads();
  if (tid == 0) {
    float tot = 0.f;
    #pragma unroll
    for (int i = 0; i < 8; i++) tot += red[i];
    s_inv = rsqrtf(tot * (1.0f / (float)Hd) + 1e-6f);
  }
  __syncthreads();
  const float inv = s_inv;
  const float4 g4 = *(const float4*)(g + tid * 4);
  float4 o4;
  o4.x = v4.x * inv * g4.x;
  o4.y = v4.y * inv * g4.y;
  o4.z = v4.z * inv * g4.z;
  o4.w = v4.w * inv * g4.w;
  *(float4*)(out + base + tid * 4) = o4;
  if (FOUT) {
    uint32_t p0 = packh(o4.x, o4.y), p1 = packh(o4.z, o4.w);
    uint2 hh; hh.x = p0; hh.y = p1;
    *(uint2*)(oh + base + tid * 4) = hh;
  }
}

// ---------------- host ----------------
static const int GEMM_SMEM = 98304;   // 3 stages x 32KB
static const int ATTN_SMEM = 73728;   // Q 8KB + 2 x 32KB

extern "C" void kernel_launch(void* const* d_in, const int* in_sizes, int n_in,
                              void* d_out, int out_size) {
  const float* x    = (const float*)d_in[0];
  const float* y    = (const float*)d_in[1];
  const float* mask = (const float*)d_in[2];
  const float* Wq   = (const float*)d_in[3];
  const float* bq   = (const float*)d_in[4];
  const float* Wk   = (const float*)d_in[5];
  const float* bk   = (const float*)d_in[6];
  const float* Wv   = (const float*)d_in[7];
  const float* bv   = (const float*)d_in[8];
  const float* Wo   = (const float*)d_in[9];
  const float* bo   = (const float*)d_in[10];
  const float* g1   = (const float*)d_in[11];
  const float* Wi   = (const float*)d_in[12];
  const float* bi   = (const float*)d_in[13];
  const float* Wo2  = (const float*)d_in[14];
  const float* bo2  = (const float*)d_in[15];
  const float* g2   = (const float*)d_in[16];
  const int*   t    = (const int*)d_in[17];
  float* out = (float*)d_out;

  cudaFuncSetAttribute(gemm_mma_kernel, cudaFuncAttributeMaxDynamicSharedMemorySize, GEMM_SMEM);
  cudaFuncSetAttribute(attn_mma_kernel, cudaFuncAttributeMaxDynamicSharedMemorySize, ATTN_SMEM);

  float *xs, *att, *tmp, *mask2;
  cudaGetSymbolAddress((void**)&xs,    g_xs);
  cudaGetSymbolAddress((void**)&att,   g_att);
  cudaGetSymbolAddress((void**)&tmp,   g_tmp);
  cudaGetSymbolAddress((void**)&mask2, g_mask2);

  __half *xh,*yh,*qh,*kh,*vh,*ch,*ah,*ih;
  cudaGetSymbolAddress((void**)&xh, g_xh);
  cudaGetSymbolAddress((void**)&yh, g_yh);
  cudaGetSymbolAddress((void**)&qh, g_qh);
  cudaGetSymbolAddress((void**)&kh, g_kh);
  cudaGetSymbolAddress((void**)&vh, g_vh);
  cudaGetSymbolAddress((void**)&ch, g_ch);
  cudaGetSymbolAddress((void**)&ah, g_ah);
  cudaGetSymbolAddress((void**)&ih, g_ih);

  __half *wq,*wk,*wv,*wo,*wi,*w2;
  cudaGetSymbolAddress((void**)&wq, g_wq);
  cudaGetSymbolAddress((void**)&wk, g_wk);
  cudaGetSymbolAddress((void**)&wv, g_wv);
  cudaGetSymbolAddress((void**)&wo, g_wo);
  cudaGetSymbolAddress((void**)&wi, g_wi);
  cudaGetSymbolAddress((void**)&w2, g_w2);

  // fused prologue: routing + weight conversion in one launch
  {
    CvtJobs jb;
    const float* Ws[6] = {Wq, Wk, Wv, Wo, Wi, Wo2};
    __half* Ts[6] = {wq, wk, wv, wo, wi, w2};
    int Ks[6] = {Hd, Hd, Hd, Hd, Hd, Id};
    int Ns[6] = {Hd, Hd, Hd, Hd, Id, Hd};
    int cum = 0;
    for (int i = 0; i < 6; i++) {
      jb.W[i] = Ws[i]; jb.T[i] = Ts[i];
      jb.K[i] = Ks[i]; jb.N[i] = Ns[i];
      jb.tilesX[i] = Ns[i] / 32;
      jb.start[i] = cum;
      cum += (Ns[i] / 32) * (Ks[i] / 32);
    }
    prologue_kernel<<<TOK + cum, 256>>>(x, y, mask, t, xs, mask2, xh, yh, jb);
  }

  const float QSCALE = 0.125f * 1.4426950408889634f;

  {
    GemmJob jq = {xh, wq, bq, nullptr, qh, QSCALE, 2, 0};
    GemmJob jk = {yh, wk, bk, nullptr, kh, 1.0f,   2, 0};
    GemmJob jv = {yh, wv, bv, nullptr, vh, 1.0f,   2, 0};
    gemm_mma_kernel<<<dim3(Hd/128, TOK/128, 3), 256, GEMM_SMEM>>>(jq, jk, jv, TOK, Hd, Hd);
  }

  attn_mma_kernel<<<dim3(16, NHh, 4), 128, ATTN_SMEM>>>(qh, kh, vh, mask2, ch);

  {
    GemmJob jo = {ch, wo, bo, tmp, nullptr, 1.0f, 0, 0};
    gemm_mma_kernel<<<dim3(Hd/128, TOK/128, 1), 256, GEMM_SMEM>>>(jo, jo, jo, TOK, Hd, Hd);
  }
  rms_kernel<true ><<<TOK, 256>>>(tmp, xs, g1, att, ah);

  {
    GemmJob ji = {ah, wi, bi, nullptr, ih, 1.0f, 2, 1};
    gemm_mma_kernel<<<dim3(Id/128, TOK/128, 1), 256, GEMM_SMEM>>>(ji, ji, ji, TOK, Id, Hd);
  }
  {
    GemmJob j2 = {ih, w2, bo2, tmp, nullptr, 1.0f, 0, 0};
    gemm_mma_kernel<<<dim3(Hd/128, TOK/128, 1), 256, GEMM_SMEM>>>(j2, j2, j2, TOK, Hd, Id);
  }
  rms_kernel<false><<<TOK, 256>>>(tmp, att, g2, out, nullptr);
}

// round 14
// speedup vs baseline: 1.5125x; 1.5125x over previous
#include <cuda_runtime.h>
#include <cuda_fp16.h>
#include <math.h>
#include <stdint.h>

#define TOK 4096        // B*S
#define Hd  1024
#define Id  4096
#define NHh 16
#define DHh 64

// ---------------- scratch (device globals; no allocs) ----------------
__device__ float g_xs [TOK * Hd];
__device__ float g_att[TOK * Hd];
__device__ float g_tmp[TOK * Hd];
__device__ float g_mask2[TOK];          // mask * log2(e)

// fp16 activation buffers
__device__ __half g_xh[TOK * Hd];
__device__ __half g_yh[TOK * Hd];
__device__ __half g_qh[TOK * Hd];
__device__ __half g_kh[TOK * Hd];
__device__ __half g_vh[TOK * Hd];
__device__ __half g_ch[TOK * Hd];
__device__ __half g_ah[TOK * Hd];
__device__ __half g_ih[TOK * Id];

// transposed fp16 weights [N, K]
__device__ __half g_wq[Hd * Hd];
__device__ __half g_wk[Hd * Hd];
__device__ __half g_wv[Hd * Hd];
__device__ __half g_wo[Hd * Hd];
__device__ __half g_wi[Id * Hd];
__device__ __half g_w2[Hd * Id];

// ---------------- helpers ----------------
__device__ __forceinline__ uint32_t smem_u32(const void* p) {
  uint32_t a;
  asm("{ .reg .u64 t; cvta.to.shared.u64 t, %1; cvt.u32.u64 %0, t; }" : "=r"(a) : "l"(p));
  return a;
}
__device__ __forceinline__ void cp_async16(uint32_t dst, const void* src) {
  asm volatile("cp.async.cg.shared.global [%0], [%1], 16;" :: "r"(dst), "l"(src) : "memory");
}
#define CP_COMMIT() asm volatile("cp.async.commit_group;" ::: "memory")
#define CP_WAIT(n)  asm volatile("cp.async.wait_group %0;" :: "n"(n) : "memory")

__device__ __forceinline__ void ldsm4(uint32_t* r, uint32_t addr) {
  asm volatile("ldmatrix.sync.aligned.m8n8.x4.shared.b16 {%0,%1,%2,%3}, [%4];"
               : "=r"(r[0]), "=r"(r[1]), "=r"(r[2]), "=r"(r[3]) : "r"(addr));
}
__device__ __forceinline__ void ldsm4t(uint32_t* r, uint32_t addr) {
  asm volatile("ldmatrix.sync.aligned.m8n8.x4.trans.shared.b16 {%0,%1,%2,%3}, [%4];"
               : "=r"(r[0]), "=r"(r[1]), "=r"(r[2]), "=r"(r[3]) : "r"(addr));
}
__device__ __forceinline__ void mma16816(float* d, const uint32_t* a, const uint32_t* b) {
  asm volatile("mma.sync.aligned.m16n8k16.row.col.f32.f16.f16.f32 "
               "{%0,%1,%2,%3}, {%4,%5,%6,%7}, {%8,%9}, {%0,%1,%2,%3};"
               : "+f"(d[0]), "+f"(d[1]), "+f"(d[2]), "+f"(d[3])
               : "r"(a[0]), "r"(a[1]), "r"(a[2]), "r"(a[3]), "r"(b[0]), "r"(b[1]));
}
__device__ __forceinline__ uint32_t packh(float a, float b) {
  __half2 t = __floats2half2_rn(a, b);
  return *(uint32_t*)&t;
}

__device__ __forceinline__ uint32_t swz128(int row, int c16) {
  return (uint32_t)(row * 128 + ((c16 ^ (row & 7)) << 4));
}

// ---------------- fused prologue: routing (blocks 0..TOK-1) + weight cvt ----------------
struct CvtJobs {
  const float* W[6];
  __half* T[6];
  int K[6], N[6], tilesX[6], start[6];  // start[] offset AFTER routing blocks
};

__global__ void __launch_bounds__(256) prologue_kernel(
    const float* __restrict__ x, const float* __restrict__ y,
    const float* __restrict__ mask, const int* __restrict__ tptr,
    float* __restrict__ xs, float* __restrict__ mask2,
    __half* __restrict__ xh, __half* __restrict__ yh,
    CvtJobs jb) {
  const int blk = blockIdx.x;
  const int tid = threadIdx.x;

  if (blk >= TOK) {
    // ---- weight conversion tile ----
    const int b = blk - TOK;
    int j = 0;
    #pragma unroll
    for (int i = 1; i < 6; i++) if (b >= jb.start[i]) j = i;
    const int local = b - jb.start[j];
    const int K = jb.K[j], N = jb.N[j];
    const int nb = (local % jb.tilesX[j]) * 32;
    const int kb = (local / jb.tilesX[j]) * 32;
    const float* W = jb.W[j];
    __half* T = jb.T[j];

    __shared__ float t[32][33];
    const int tx = tid & 31, ty = tid >> 5;
    #pragma unroll
    for (int i = 0; i < 32; i += 8)
      t[ty + i][tx] = W[(size_t)(kb + ty + i) * N + nb + tx];
    __syncthreads();
    #pragma unroll
    for (int i = 0; i < 32; i += 8)
      T[(size_t)(nb + ty + i) * K + kb + tx] = __float2half_rn(t[tx][ty + i]);
    return;
  }

  // ---- routing (vectorized float4 I/O) ----
  const int token = blk;
  const long base = (long)token * Hd;
  if (tid == 32) mask2[token] = mask[token] * 1.4426950408889634f;

  const float4 x4 = *(const float4*)(x + base + tid * 4);
  const float4 y4 = *(const float4*)(y + base + tid * 4);
  float sxx = x4.x*x4.x + x4.y*x4.y + x4.z*x4.z + x4.w*x4.w;
  float sxy = x4.x*y4.x + x4.y*y4.y + x4.z*y4.z + x4.w*y4.w;
  float syy = y4.x*y4.x + y4.y*y4.y + y4.z*y4.z + y4.w*y4.w;

  #pragma unroll
  for (int o = 16; o; o >>= 1) {
    sxx += __shfl_xor_sync(0xffffffffu, sxx, o);
    sxy += __shfl_xor_sync(0xffffffffu, sxy, o);
    syy += __shfl_xor_sync(0xffffffffu, syy, o);
  }
  __shared__ float red[8][3];
  __shared__ float sc[2];
  if ((tid & 31) == 0) { red[tid >> 5][0] = sxx; red[tid >> 5][1] = sxy; red[tid >> 5][2] = syy; }
  __syncthreads();
  if (tid == 0) {
    float a = 0.f, bb = 0.f, c = 0.f;
    #pragma unroll
    for (int i = 0; i < 8; i++) { a += red[i][0]; bb += red[i][1]; c += red[i][2]; }
    const int t = *tptr;
    float b1 = 0.f, b2 = 0.f, c1 = 0.5f, c2 = 0.5f;
    for (int it = 0; it < t; it++) {
      if (it > 0) {
        float mm = fmaxf(b1, b2);
        float e1 = expf(b1 - mm), e2 = expf(b2 - mm);
        float inv = 1.0f / (e1 + e2);
        c1 = e1 * inv; c2 = e2 * inv;
      }
      float vv = c1 * c1 * a + 2.0f * c1 * c2 * bb + c2 * c2 * c;
      float n  = sqrtf(vv);
      float f  = n / (1.0f + vv);
      b1 += f * (c1 * a  + c2 * bb);
      b2 += f * (c1 * bb + c2 * c );
    }
    sc[0] = c1; sc[1] = c2;
  }
  __syncthreads();
  const float c1 = sc[0], c2 = sc[1];
  float4 vx4;
  vx4.x = c1 * x4.x; vx4.y = c1 * x4.y; vx4.z = c1 * x4.z; vx4.w = c1 * x4.w;
  *(float4*)(xs + base + tid * 4) = vx4;
  uint2 hx; hx.x = packh(vx4.x, vx4.y); hx.y = packh(vx4.z, vx4.w);
  *(uint2*)(xh + base + tid * 4) = hx;
  uint2 hy; hy.x = packh(c2 * y4.x, c2 * y4.y); hy.y = packh(c2 * y4.z, c2 * y4.w);
  *(uint2*)(yh + base + tid * 4) = hy;
}

// ---------------- HMMA GEMM (R9 winner config, frozen) ----------------
struct GemmJob {
  const __half *A, *B;
  const float* bias;
  float* C;
  __half* Ch;
  float oscale;
  int outmode;   // 0: fp32 C; 2: fp16 Ch
  int gelu;
};

__global__ void __launch_bounds__(256, 2)
gemm_mma_kernel(GemmJob j0, GemmJob j1, GemmJob j2, int M, int N, int K) {
  extern __shared__ __align__(128) char sm[];
  const uint32_t smb = smem_u32(sm);
  const GemmJob j = (blockIdx.z == 0) ? j0 : ((blockIdx.z == 1) ? j1 : j2);
  const int tid = threadIdx.x;
  const int wid = tid >> 5, lane = tid & 31;
  const int bm = blockIdx.y * 128, bn = blockIdx.x * 128;
  const int warp_m = wid & 1, warp_n = wid >> 1;
  const int NK = K >> 6;

  auto soA = [](int s) -> uint32_t { return (uint32_t)(s * 32768); };
  auto soB = [](int s) -> uint32_t { return (uint32_t)(s * 32768 + 16384); };

  auto load_stage = [&](int kt, int s) {
    const int koff = kt * 64;
    #pragma unroll
    for (int jj = 0; jj < 4; jj++) {
      const int ch = tid + jj * 256;
      const int row = ch >> 3, c = ch & 7;
      const uint32_t d = swz128(row, c);
      cp_async16(smb + soA(s) + d, j.A + (size_t)(bm + row) * K + koff + c * 8);
      cp_async16(smb + soB(s) + d, j.B + (size_t)(bn + row) * K + koff + c * 8);
    }
  };

  float acc[4][4][4];
  #pragma unroll
  for (int i = 0; i < 4; i++)
    #pragma unroll
    for (int jj = 0; jj < 4; jj++)
      #pragma unroll
      for (int q = 0; q < 4; q++) acc[i][jj][q] = 0.f;

  load_stage(0, 0); CP_COMMIT();
  load_stage(1, 1); CP_COMMIT();

  const int la_row = (lane & 7) + ((lane >> 3) & 1) * 8;
  const int la_c   = (lane >> 4);
  const int lb_row = (lane & 7) + (lane >> 4) * 8;
  const int lb_c   = (lane >> 3) & 1;

  int s = 0;
  for (int kt = 0; kt < NK; kt++) {
    if (kt + 1 < NK) { CP_WAIT(1); } else { CP_WAIT(0); }
    __syncthreads();
    if (kt + 2 < NK) { load_stage(kt + 2, (s + 2 > 2) ? s - 1 : s + 2); CP_COMMIT(); }

    const uint32_t baseA = smb + soA(s);
    const uint32_t baseB = smb + soB(s);

    #pragma unroll
    for (int ks = 0; ks < 4; ks++) {
      uint32_t a4[4][4], b4[2][4];
      #pragma unroll
      for (int tm = 0; tm < 4; tm++)
        ldsm4(a4[tm], baseA + swz128(warp_m * 64 + tm * 16 + la_row, ks * 2 + la_c));
      #pragma unroll
      for (int tn2 = 0; tn2 < 2; tn2++)
        ldsm4(b4[tn2], baseB + swz128(warp_n * 32 + tn2 * 16 + lb_row, ks * 2 + lb_c));
      #pragma unroll
      for (int tm = 0; tm < 4; tm++)
        #pragma unroll
        for (int tn = 0; tn < 4; tn++)
          mma16816(acc[tm][tn], a4[tm], &b4[tn >> 1][(tn & 1) * 2]);
    }
    s = (s == 2) ? 0 : s + 1;
  }

  const int g = lane >> 2, tq = lane & 3;
  #pragma unroll
  for (int tm = 0; tm < 4; tm++) {
    #pragma unroll
    for (int tn = 0; tn < 4; tn++) {
      const int col = bn + warp_n * 32 + tn * 8 + tq * 2;
      const float b0 = j.bias[col], b1 = j.bias[col + 1];
      #pragma unroll
      for (int half = 0; half < 2; half++) {
        const int row = bm + warp_m * 64 + tm * 16 + g + half * 8;
        float vx = (acc[tm][tn][half * 2 + 0] + b0) * j.oscale;
        float vy = (acc[tm][tn][half * 2 + 1] + b1) * j.oscale;
        if (j.gelu) {
          vx = 0.5f * vx * (1.0f + erff(vx * 0.7071067811865476f));
          vy = 0.5f * vy * (1.0f + erff(vy * 0.7071067811865476f));
        }
        if (j.outmode == 0) {
          float2 v; v.x = vx; v.y = vy;
          *(float2*)(j.C + (size_t)row * N + col) = v;
        } else {
          *(uint32_t*)(j.Ch + (size_t)row * N + col) = packh(vx, vy);
        }
      }
    }
  }
}

// ---------------- HMMA flash attention (fp16, fp32 accum, exp2-space, 3-stage KV) ----------------
// smem: Q 8KB + 3 x (K 8KB + V 8KB) = 56KB. 2 CTAs/SM.
__global__ void __launch_bounds__(128, 2)
attn_mma_kernel(const __half* __restrict__ Qh,
                const __half* __restrict__ Kh, const __half* __restrict__ Vh,
                const float* __restrict__ mask2,
                __half* __restrict__ Ch) {
  extern __shared__ __align__(128) char sm[];
  const uint32_t smb = smem_u32(sm);
  const int tid = threadIdx.x;
  const int warp = tid >> 5, lane = tid & 31;
  const int qt = blockIdx.x, h = blockIdx.y, b = blockIdx.z;
  const int g = lane >> 2, tq = lane & 3;

  const int la_row = (lane & 7) + ((lane >> 3) & 1) * 8;
  const int la_c   = (lane >> 4);
  const int lb_row = (lane & 7) + (lane >> 4) * 8;
  const int lb_c   = (lane >> 3) & 1;
  const int lv_row = (lane & 7) + ((lane >> 3) & 1) * 8;
  const int lv_c   = (lane >> 4);

  {
    #pragma unroll
    for (int jj = 0; jj < 4; jj++) {
      const int ch = tid + jj * 128;
      const int row = ch >> 3, c = ch & 7;
      cp_async16(smb + swz128(row, c),
                 Qh + (size_t)(b * 1024 + qt * 64 + row) * Hd + h * 64 + c * 8);
    }
  }
  auto load_kv = [&](int kt, int s) {
    const uint32_t so = smb + 8192 + s * 16384;
    #pragma unroll
    for (int jj = 0; jj < 4; jj++) {
      const int ch = tid + jj * 128;
      const int row = ch >> 3, c = ch & 7;
      const uint32_t d = swz128(row, c);
      const size_t gk = (size_t)(b * 1024 + kt * 64 + row) * Hd + h * 64 + c * 8;
      cp_async16(so + d,        Kh + gk);
      cp_async16(so + 8192 + d, Vh + gk);
    }
  };
  load_kv(0, 0); CP_COMMIT();
  load_kv(1, 1); CP_COMMIT();

  float m0 = -1e30f, m1 = -1e30f, l0 = 0.f, l1 = 0.f;
  float oacc[8][4];
  #pragma unroll
  for (int jj = 0; jj < 8; jj++)
    #pragma unroll
    for (int q = 0; q < 4; q++) oacc[jj][q] = 0.f;

  int s = 0;
  for (int kt = 0; kt < 16; kt++) {
    if (kt + 2 < 16) { load_kv(kt + 2, (s + 2 > 2) ? s - 1 : s + 2); CP_COMMIT(); }
    const int rem = 15 - kt;
    if (rem >= 2) { CP_WAIT(2); } else if (rem == 1) { CP_WAIT(1); } else { CP_WAIT(0); }
    __syncthreads();

    const uint32_t sK = smb + 8192 + s * 16384;
    const uint32_t sV = sK + 8192;

    float sacc[8][4];
    #pragma unroll
    for (int jj = 0; jj < 8; jj++)
      #pragma unroll
      for (int q = 0; q < 4; q++) sacc[jj][q] = 0.f;

    #pragma unroll
    for (int kc = 0; kc < 4; kc++) {
      uint32_t q4[4];
      ldsm4(q4, smb + swz128(warp * 16 + la_row, kc * 2 + la_c));
      #pragma unroll
      for (int n16 = 0; n16 < 4; n16++) {
        uint32_t k4[4];
        ldsm4(k4, sK + swz128(n16 * 16 + lb_row, kc * 2 + lb_c));
        mma16816(sacc[2 * n16],     q4, k4);
        mma16816(sacc[2 * n16 + 1], q4, k4 + 2);
      }
    }

    const float* mrow = mask2 + b * 1024 + kt * 64;
    float mx0 = -1e30f, mx1 = -1e30f;
    #pragma unroll
    for (int jj = 0; jj < 8; jj++) {
      const float2 mv = *(const float2*)(mrow + jj * 8 + 2 * tq);
      sacc[jj][0] += mv.x;
      sacc[jj][1] += mv.y;
      sacc[jj][2] += mv.x;
      sacc[jj][3] += mv.y;
      mx0 = fmaxf(mx0, fmaxf(sacc[jj][0], sacc[jj][1]));
      mx1 = fmaxf(mx1, fmaxf(sacc[jj][2], sacc[jj][3]));
    }
    mx0 = fmaxf(mx0, __shfl_xor_sync(0xffffffffu, mx0, 1));
    mx0 = fmaxf(mx0, __shfl_xor_sync(0xffffffffu, mx0, 2));
    mx1 = fmaxf(mx1, __shfl_xor_sync(0xffffffffu, mx1, 1));
    mx1 = fmaxf(mx1, __shfl_xor_sync(0xffffffffu, mx1, 2));
    const float mn0 = fmaxf(m0, mx0), mn1 = fmaxf(m1, mx1);
    const float rs0 = exp2f(m0 - mn0), rs1 = exp2f(m1 - mn1);
    m0 = mn0; m1 = mn1;

    float sum0 = 0.f, sum1 = 0.f;
    uint32_t ph01[8], ph23[8];
    #pragma unroll
    for (int jj = 0; jj < 8; jj++) {
      const float p0 = exp2f(sacc[jj][0] - mn0), p1 = exp2f(sacc[jj][1] - mn0);
      const float p2 = exp2f(sacc[jj][2] - mn1), p3 = exp2f(sacc[jj][3] - mn1);
      sum0 += p0 + p1; sum1 += p2 + p3;
      ph01[jj] = packh(p0, p1);
      ph23[jj] = packh(p2, p3);
      oacc[jj][0] *= rs0; oacc[jj][1] *= rs0;
      oacc[jj][2] *= rs1; oacc[jj][3] *= rs1;
    }
    sum0 += __shfl_xor_sync(0xffffffffu, sum0, 1);
    sum0 += __shfl_xor_sync(0xffffffffu, sum0, 2);
    sum1 += __shfl_xor_sync(0xffffffffu, sum1, 1);
    sum1 += __shfl_xor_sync(0xffffffffu, sum1, 2);
    l0 = l0 * rs0 + sum0;
    l1 = l1 * rs1 + sum1;

    #pragma unroll
    for (int kc = 0; kc < 4; kc++) {
      uint32_t ah[4] = {ph01[2*kc], ph23[2*kc], ph01[2*kc+1], ph23[2*kc+1]};
      #pragma unroll
      for (int n16 = 0; n16 < 4; n16++) {
        uint32_t v4[4];
        ldsm4t(v4, sV + swz128(kc * 16 + lv_row, n16 * 2 + lv_c));
        mma16816(oacc[2 * n16],     ah, v4);
        mma16816(oacc[2 * n16 + 1], ah, v4 + 2);
      }
    }
    __syncthreads();
    s = (s == 2) ? 0 : s + 1;
  }

  const float inv0 = 1.f / l0, inv1 = 1.f / l1;
  const int row0 = b * 1024 + qt * 64 + warp * 16 + g;
  #pragma unroll
  for (int jj = 0; jj < 8; jj++) {
    const int col = h * 64 + (jj >> 1) * 16 + (jj & 1) * 8 + 2 * tq;
    *(uint32_t*)(Ch + (size_t)row0 * Hd + col)       = packh(oacc[jj][0] * inv0, oacc[jj][1] * inv0);
    *(uint32_t*)(Ch + (size_t)(row0 + 8) * Hd + col) = packh(oacc[jj][2] * inv1, oacc[jj][3] * inv1);
  }
}

// ---------------- fused residual + RMSNorm (float4 vectorized) ----------------
template<bool FOUT>
__global__ void __launch_bounds__(256) rms_kernel(
    const float* __restrict__ in, const float* __restrict__ res,
    const float* __restrict__ g, float* __restrict__ out,
    __half* __restrict__ oh) {
  const int row = blockIdx.x, tid = threadIdx.x;
  __shared__ float red[8];
  __shared__ float s_inv;
  const long base = (long)row * Hd;

  float4 v4 = *(const float4*)(in + base + tid * 4);
  const float4 r4 = *(const float4*)(res + base + tid * 4);
  v4.x += r4.x; v4.y += r4.y; v4.z += r4.z; v4.w += r4.w;
  float ss = v4.x * v4.x + v4.y * v4.y + v4.z * v4.z + v4.w * v4.w;

  #pragma unroll
  for (int o = 16; o; o >>= 1) ss += __shfl_xor_sync(0xffffffffu, ss, o);
  if ((tid & 31) == 0) red[tid >> 5] = ss;
  __syncthreads();
  if (tid == 0) {
    float tot = 0.f;
    #pragma unroll
    for (int i = 0; i < 8; i++) tot += red[i];
    s_inv = rsqrtf(tot * (1.0f / (float)Hd) + 1e-6f);
  }
  __syncthreads();
  const float inv = s_inv;
  const float4 g4 = *(const float4*)(g + tid * 4);
  float4 o4;
  o4.x = v4.x * inv * g4.x;
  o4.y = v4.y * inv * g4.y;
  o4.z = v4.z * inv * g4.z;
  o4.w = v4.w * inv * g4.w;
  *(float4*)(out + base + tid * 4) = o4;
  if (FOUT) {
    uint32_t p0 = packh(o4.x, o4.y), p1 = packh(o4.z, o4.w);
    uint2 hh; hh.x = p0; hh.y = p1;
    *(uint2*)(oh + base + tid * 4) = hh;
  }
}

// ---------------- host ----------------
static const int GEMM_SMEM = 98304;   // 3 stages x 32KB
static const int ATTN_SMEM = 57344;   // Q 8KB + 3 x 16KB

extern "C" void kernel_launch(void* const* d_in, const int* in_sizes, int n_in,
                              void* d_out, int out_size) {
  const float* x    = (const float*)d_in[0];
  const float* y    = (const float*)d_in[1];
  const float* mask = (const float*)d_in[2];
  const float* Wq   = (const float*)d_in[3];
  const float* bq   = (const float*)d_in[4];
  const float* Wk   = (const float*)d_in[5];
  const float* bk   = (const float*)d_in[6];
  const float* Wv   = (const float*)d_in[7];
  const float* bv   = (const float*)d_in[8];
  const float* Wo   = (const float*)d_in[9];
  const float* bo   = (const float*)d_in[10];
  const float* g1   = (const float*)d_in[11];
  const float* Wi   = (const float*)d_in[12];
  const float* bi   = (const float*)d_in[13];
  const float* Wo2  = (const float*)d_in[14];
  const float* bo2  = (const float*)d_in[15];
  const float* g2   = (const float*)d_in[16];
  const int*   t    = (const int*)d_in[17];
  float* out = (float*)d_out;

  cudaFuncSetAttribute(gemm_mma_kernel, cudaFuncAttributeMaxDynamicSharedMemorySize, GEMM_SMEM);
  cudaFuncSetAttribute(attn_mma_kernel, cudaFuncAttributeMaxDynamicSharedMemorySize, ATTN_SMEM);

  float *xs, *att, *tmp, *mask2;
  cudaGetSymbolAddress((void**)&xs,    g_xs);
  cudaGetSymbolAddress((void**)&att,   g_att);
  cudaGetSymbolAddress((void**)&tmp,   g_tmp);
  cudaGetSymbolAddress((void**)&mask2, g_mask2);

  __half *xh,*yh,*qh,*kh,*vh,*ch,*ah,*ih;
  cudaGetSymbolAddress((void**)&xh, g_xh);
  cudaGetSymbolAddress((void**)&yh, g_yh);
  cudaGetSymbolAddress((void**)&qh, g_qh);
  cudaGetSymbolAddress((void**)&kh, g_kh);
  cudaGetSymbolAddress((void**)&vh, g_vh);
  cudaGetSymbolAddress((void**)&ch, g_ch);
  cudaGetSymbolAddress((void**)&ah, g_ah);
  cudaGetSymbolAddress((void**)&ih, g_ih);

  __half *wq,*wk,*wv,*wo,*wi,*w2;
  cudaGetSymbolAddress((void**)&wq, g_wq);
  cudaGetSymbolAddress((void**)&wk, g_wk);
  cudaGetSymbolAddress((void**)&wv, g_wv);
  cudaGetSymbolAddress((void**)&wo, g_wo);
  cudaGetSymbolAddress((void**)&wi, g_wi);
  cudaGetSymbolAddress((void**)&w2, g_w2);

  // fused prologue: routing + weight conversion in one launch
  {
    CvtJobs jb;
    const float* Ws[6] = {Wq, Wk, Wv, Wo, Wi, Wo2};
    __half* Ts[6] = {wq, wk, wv, wo, wi, w2};
    int Ks[6] = {Hd, Hd, Hd, Hd, Hd, Id};
    int Ns[6] = {Hd, Hd, Hd, Hd, Id, Hd};
    int cum = 0;
    for (int i = 0; i < 6; i++) {
      jb.W[i] = Ws[i]; jb.T[i] = Ts[i];
      jb.K[i] = Ks[i]; jb.N[i] = Ns[i];
      jb.tilesX[i] = Ns[i] / 32;
      jb.start[i] = cum;
      cum += (Ns[i] / 32) * (Ks[i] / 32);
    }
    prologue_kernel<<<TOK + cum, 256>>>(x, y, mask, t, xs, mask2, xh, yh, jb);
  }

  const float QSCALE = 0.125f * 1.4426950408889634f;

  {
    GemmJob jq = {xh, wq, bq, nullptr, qh, QSCALE, 2, 0};
    GemmJob jk = {yh, wk, bk, nullptr, kh, 1.0f,   2, 0};
    GemmJob jv = {yh, wv, bv, nullptr, vh, 1.0f,   2, 0};
    gemm_mma_kernel<<<dim3(Hd/128, TOK/128, 3), 256, GEMM_SMEM>>>(jq, jk, jv, TOK, Hd, Hd);
  }

  attn_mma_kernel<<<dim3(16, NHh, 4), 128, ATTN_SMEM>>>(qh, kh, vh, mask2, ch);

  {
    GemmJob jo = {ch, wo, bo, tmp, nullptr, 1.0f, 0, 0};
    gemm_mma_kernel<<<dim3(Hd/128, TOK/128, 1), 256, GEMM_SMEM>>>(jo, jo, jo, TOK, Hd, Hd);
  }
  rms_kernel<true ><<<TOK, 256>>>(tmp, xs, g1, att, ah);

  {
    GemmJob ji = {ah, wi, bi, nullptr, ih, 1.0f, 2, 1};
    gemm_mma_kernel<<<dim3(Id/128, TOK/128, 1), 256, GEMM_SMEM>>>(ji, ji, ji, TOK, Id, Hd);
  }
  {
    GemmJob j2 = {ih, w2, bo2, tmp, nullptr, 1.0f, 0, 0};
    gemm_mma_kernel<<<dim3(Hd/128, TOK/128, 1), 256, GEMM_SMEM>>>(j2, j2, j2, TOK, Hd, Id);
  }
  rms_kernel<false><<<TOK, 256>>>(tmp, att, g2, out, nullptr);
}

// round 15
// speedup vs baseline: 1.5276x; 1.0100x over previous
#include <cuda_runtime.h>
#include <cuda_fp16.h>
#include <math.h>
#include <stdint.h>

#define TOK 4096        // B*S
#define Hd  1024
#define Id  4096
#define NHh 16
#define DHh 64

// ---------------- scratch (device globals; no allocs) ----------------
__device__ float g_xs [TOK * Hd];
__device__ float g_att[TOK * Hd];
__device__ float g_tmp[TOK * Hd];
__device__ float g_mask2[TOK];          // mask * log2(e)

// fp16 activation buffers
__device__ __half g_xh[TOK * Hd];
__device__ __half g_yh[TOK * Hd];
__device__ __half g_qh[TOK * Hd];
__device__ __half g_kh[TOK * Hd];
__device__ __half g_vh[TOK * Hd];
__device__ __half g_ch[TOK * Hd];
__device__ __half g_ah[TOK * Hd];
__device__ __half g_ih[TOK * Id];

// transposed fp16 weights [N, K]
__device__ __half g_wq[Hd * Hd];
__device__ __half g_wk[Hd * Hd];
__device__ __half g_wv[Hd * Hd];
__device__ __half g_wo[Hd * Hd];
__device__ __half g_wi[Id * Hd];
__device__ __half g_w2[Hd * Id];

// ---------------- helpers ----------------
__device__ __forceinline__ uint32_t smem_u32(const void* p) {
  uint32_t a;
  asm("{ .reg .u64 t; cvta.to.shared.u64 t, %1; cvt.u32.u64 %0, t; }" : "=r"(a) : "l"(p));
  return a;
}
__device__ __forceinline__ void cp_async16(uint32_t dst, const void* src) {
  asm volatile("cp.async.cg.shared.global [%0], [%1], 16;" :: "r"(dst), "l"(src) : "memory");
}
#define CP_COMMIT() asm volatile("cp.async.commit_group;" ::: "memory")
#define CP_WAIT(n)  asm volatile("cp.async.wait_group %0;" :: "n"(n) : "memory")

__device__ __forceinline__ void ldsm4(uint32_t* r, uint32_t addr) {
  asm volatile("ldmatrix.sync.aligned.m8n8.x4.shared.b16 {%0,%1,%2,%3}, [%4];"
               : "=r"(r[0]), "=r"(r[1]), "=r"(r[2]), "=r"(r[3]) : "r"(addr));
}
__device__ __forceinline__ void ldsm4t(uint32_t* r, uint32_t addr) {
  asm volatile("ldmatrix.sync.aligned.m8n8.x4.trans.shared.b16 {%0,%1,%2,%3}, [%4];"
               : "=r"(r[0]), "=r"(r[1]), "=r"(r[2]), "=r"(r[3]) : "r"(addr));
}
__device__ __forceinline__ void mma16816(float* d, const uint32_t* a, const uint32_t* b) {
  asm volatile("mma.sync.aligned.m16n8k16.row.col.f32.f16.f16.f32 "
               "{%0,%1,%2,%3}, {%4,%5,%6,%7}, {%8,%9}, {%0,%1,%2,%3};"
               : "+f"(d[0]), "+f"(d[1]), "+f"(d[2]), "+f"(d[3])
               : "r"(a[0]), "r"(a[1]), "r"(a[2]), "r"(a[3]), "r"(b[0]), "r"(b[1]));
}
__device__ __forceinline__ uint32_t packh(float a, float b) {
  __half2 t = __floats2half2_rn(a, b);
  return *(uint32_t*)&t;
}

__device__ __forceinline__ uint32_t swz128(int row, int c16) {
  return (uint32_t)(row * 128 + ((c16 ^ (row & 7)) << 4));
}

// ---------------- fused prologue: routing (blocks 0..TOK-1) + weight cvt ----------------
struct CvtJobs {
  const float* W[6];
  __half* T[6];
  int K[6], N[6], tilesX[6], start[6];
};

__global__ void __launch_bounds__(256) prologue_kernel(
    const float* __restrict__ x, const float* __restrict__ y,
    const float* __restrict__ mask, const int* __restrict__ tptr,
    float* __restrict__ xs, float* __restrict__ mask2,
    __half* __restrict__ xh, __half* __restrict__ yh,
    CvtJobs jb) {
  const int blk = blockIdx.x;
  const int tid = threadIdx.x;

  if (blk >= TOK) {
    const int b = blk - TOK;
    int j = 0;
    #pragma unroll
    for (int i = 1; i < 6; i++) if (b >= jb.start[i]) j = i;
    const int local = b - jb.start[j];
    const int K = jb.K[j], N = jb.N[j];
    const int nb = (local % jb.tilesX[j]) * 32;
    const int kb = (local / jb.tilesX[j]) * 32;
    const float* W = jb.W[j];
    __half* T = jb.T[j];

    __shared__ float t[32][33];
    const int tx = tid & 31, ty = tid >> 5;
    #pragma unroll
    for (int i = 0; i < 32; i += 8)
      t[ty + i][tx] = W[(size_t)(kb + ty + i) * N + nb + tx];
    __syncthreads();
    #pragma unroll
    for (int i = 0; i < 32; i += 8)
      T[(size_t)(nb + ty + i) * K + kb + tx] = __float2half_rn(t[tx][ty + i]);
    return;
  }

  // routing (vectorized float4 I/O)
  const int token = blk;
  const long base = (long)token * Hd;
  if (tid == 32) mask2[token] = mask[token] * 1.4426950408889634f;

  const float4 x4 = *(const float4*)(x + base + tid * 4);
  const float4 y4 = *(const float4*)(y + base + tid * 4);
  float sxx = x4.x*x4.x + x4.y*x4.y + x4.z*x4.z + x4.w*x4.w;
  float sxy = x4.x*y4.x + x4.y*y4.y + x4.z*y4.z + x4.w*y4.w;
  float syy = y4.x*y4.x + y4.y*y4.y + y4.z*y4.z + y4.w*y4.w;

  #pragma unroll
  for (int o = 16; o; o >>= 1) {
    sxx += __shfl_xor_sync(0xffffffffu, sxx, o);
    sxy += __shfl_xor_sync(0xffffffffu, sxy, o);
    syy += __shfl_xor_sync(0xffffffffu, syy, o);
  }
  __shared__ float red[8][3];
  __shared__ float sc[2];
  if ((tid & 31) == 0) { red[tid >> 5][0] = sxx; red[tid >> 5][1] = sxy; red[tid >> 5][2] = syy; }
  __syncthreads();
  if (tid == 0) {
    float a = 0.f, bb = 0.f, c = 0.f;
    #pragma unroll
    for (int i = 0; i < 8; i++) { a += red[i][0]; bb += red[i][1]; c += red[i][2]; }
    const int t = *tptr;
    float b1 = 0.f, b2 = 0.f, c1 = 0.5f, c2 = 0.5f;
    for (int it = 0; it < t; it++) {
      if (it > 0) {
        float mm = fmaxf(b1, b2);
        float e1 = expf(b1 - mm), e2 = expf(b2 - mm);
        float inv = 1.0f / (e1 + e2);
        c1 = e1 * inv; c2 = e2 * inv;
      }
      float vv = c1 * c1 * a + 2.0f * c1 * c2 * bb + c2 * c2 * c;
      float n  = sqrtf(vv);
      float f  = n / (1.0f + vv);
      b1 += f * (c1 * a  + c2 * bb);
      b2 += f * (c1 * bb + c2 * c );
    }
    sc[0] = c1; sc[1] = c2;
  }
  __syncthreads();
  const float c1 = sc[0], c2 = sc[1];
  float4 vx4;
  vx4.x = c1 * x4.x; vx4.y = c1 * x4.y; vx4.z = c1 * x4.z; vx4.w = c1 * x4.w;
  *(float4*)(xs + base + tid * 4) = vx4;
  uint2 hx; hx.x = packh(vx4.x, vx4.y); hx.y = packh(vx4.z, vx4.w);
  *(uint2*)(xh + base + tid * 4) = hx;
  uint2 hy; hy.x = packh(c2 * y4.x, c2 * y4.y); hy.y = packh(c2 * y4.z, c2 * y4.w);
  *(uint2*)(yh + base + tid * 4) = hy;
}

// ---------------- HMMA GEMM (R9 winner config, frozen) ----------------
struct GemmJob {
  const __half *A, *B;
  const float* bias;
  float* C;
  __half* Ch;
  float oscale;
  int outmode;   // 0: fp32 C; 2: fp16 Ch
  int gelu;
};

__global__ void __launch_bounds__(256, 2)
gemm_mma_kernel(GemmJob j0, GemmJob j1, GemmJob j2, int M, int N, int K) {
  extern __shared__ __align__(128) char sm[];
  const uint32_t smb = smem_u32(sm);
  const GemmJob j = (blockIdx.z == 0) ? j0 : ((blockIdx.z == 1) ? j1 : j2);
  const int tid = threadIdx.x;
  const int wid = tid >> 5, lane = tid & 31;
  const int bm = blockIdx.y * 128, bn = blockIdx.x * 128;
  const int warp_m = wid & 1, warp_n = wid >> 1;
  const int NK = K >> 6;

  auto soA = [](int s) -> uint32_t { return (uint32_t)(s * 32768); };
  auto soB = [](int s) -> uint32_t { return (uint32_t)(s * 32768 + 16384); };

  auto load_stage = [&](int kt, int s) {
    const int koff = kt * 64;
    #pragma unroll
    for (int jj = 0; jj < 4; jj++) {
      const int ch = tid + jj * 256;
      const int row = ch >> 3, c = ch & 7;
      const uint32_t d = swz128(row, c);
      cp_async16(smb + soA(s) + d, j.A + (size_t)(bm + row) * K + koff + c * 8);
      cp_async16(smb + soB(s) + d, j.B + (size_t)(bn + row) * K + koff + c * 8);
    }
  };

  float acc[4][4][4];
  #pragma unroll
  for (int i = 0; i < 4; i++)
    #pragma unroll
    for (int jj = 0; jj < 4; jj++)
      #pragma unroll
      for (int q = 0; q < 4; q++) acc[i][jj][q] = 0.f;

  load_stage(0, 0); CP_COMMIT();
  load_stage(1, 1); CP_COMMIT();

  const int la_row = (lane & 7) + ((lane >> 3) & 1) * 8;
  const int la_c   = (lane >> 4);
  const int lb_row = (lane & 7) + (lane >> 4) * 8;
  const int lb_c   = (lane >> 3) & 1;

  int s = 0;
  for (int kt = 0; kt < NK; kt++) {
    if (kt + 1 < NK) { CP_WAIT(1); } else { CP_WAIT(0); }
    __syncthreads();
    if (kt + 2 < NK) { load_stage(kt + 2, (s + 2 > 2) ? s - 1 : s + 2); CP_COMMIT(); }

    const uint32_t baseA = smb + soA(s);
    const uint32_t baseB = smb + soB(s);

    #pragma unroll
    for (int ks = 0; ks < 4; ks++) {
      uint32_t a4[4][4], b4[2][4];
      #pragma unroll
      for (int tm = 0; tm < 4; tm++)
        ldsm4(a4[tm], baseA + swz128(warp_m * 64 + tm * 16 + la_row, ks * 2 + la_c));
      #pragma unroll
      for (int tn2 = 0; tn2 < 2; tn2++)
        ldsm4(b4[tn2], baseB + swz128(warp_n * 32 + tn2 * 16 + lb_row, ks * 2 + lb_c));
      #pragma unroll
      for (int tm = 0; tm < 4; tm++)
        #pragma unroll
        for (int tn = 0; tn < 4; tn++)
          mma16816(acc[tm][tn], a4[tm], &b4[tn >> 1][(tn & 1) * 2]);
    }
    s = (s == 2) ? 0 : s + 1;
  }

  const int g = lane >> 2, tq = lane & 3;
  #pragma unroll
  for (int tm = 0; tm < 4; tm++) {
    #pragma unroll
    for (int tn = 0; tn < 4; tn++) {
      const int col = bn + warp_n * 32 + tn * 8 + tq * 2;
      const float b0 = j.bias[col], b1 = j.bias[col + 1];
      #pragma unroll
      for (int half = 0; half < 2; half++) {
        const int row = bm + warp_m * 64 + tm * 16 + g + half * 8;
        float vx = (acc[tm][tn][half * 2 + 0] + b0) * j.oscale;
        float vy = (acc[tm][tn][half * 2 + 1] + b1) * j.oscale;
        if (j.gelu) {
          vx = 0.5f * vx * (1.0f + erff(vx * 0.7071067811865476f));
          vy = 0.5f * vy * (1.0f + erff(vy * 0.7071067811865476f));
        }
        if (j.outmode == 0) {
          float2 v; v.x = vx; v.y = vy;
          *(float2*)(j.C + (size_t)row * N + col) = v;
        } else {
          *(uint32_t*)(j.Ch + (size_t)row * N + col) = packh(vx, vy);
        }
      }
    }
  }
}

// ---------------- persistent HMMA flash attention ----------------
// grid = 296 CTAs; each loops over (qt,h,b) tiles. 3-stage KV ring per tile.
// smem: Q 8KB + 3 x (K 8KB + V 8KB) = 56KB. 2 CTAs/SM.
#define ATTN_TILES 1024
#define ATTN_GRID  296

__global__ void __launch_bounds__(128, 2)
attn_mma_kernel(const __half* __restrict__ Qh,
                const __half* __restrict__ Kh, const __half* __restrict__ Vh,
                const float* __restrict__ mask2,
                __half* __restrict__ Ch) {
  extern __shared__ __align__(128) char sm[];
  const uint32_t smb = smem_u32(sm);
  const int tid = threadIdx.x;
  const int warp = tid >> 5, lane = tid & 31;
  const int g = lane >> 2, tq = lane & 3;

  const int la_row = (lane & 7) + ((lane >> 3) & 1) * 8;
  const int la_c   = (lane >> 4);
  const int lb_row = (lane & 7) + (lane >> 4) * 8;
  const int lb_c   = (lane >> 3) & 1;
  const int lv_row = (lane & 7) + ((lane >> 3) & 1) * 8;
  const int lv_c   = (lane >> 4);

  for (int tile = blockIdx.x; tile < ATTN_TILES; tile += ATTN_GRID) {
    const int qt = tile & 15;
    const int h  = (tile >> 4) & 15;
    const int b  = tile >> 8;

    // Q load (bundled with kv0 commit)
    {
      #pragma unroll
      for (int jj = 0; jj < 4; jj++) {
        const int ch = tid + jj * 128;
        const int row = ch >> 3, c = ch & 7;
        cp_async16(smb + swz128(row, c),
                   Qh + (size_t)(b * 1024 + qt * 64 + row) * Hd + h * 64 + c * 8);
      }
    }
    auto load_kv = [&](int kt, int s) {
      const uint32_t so = smb + 8192 + s * 16384;
      #pragma unroll
      for (int jj = 0; jj < 4; jj++) {
        const int ch = tid + jj * 128;
        const int row = ch >> 3, c = ch & 7;
        const uint32_t d = swz128(row, c);
        const size_t gk = (size_t)(b * 1024 + kt * 64 + row) * Hd + h * 64 + c * 8;
        cp_async16(so + d,        Kh + gk);
        cp_async16(so + 8192 + d, Vh + gk);
      }
    };
    load_kv(0, 0); CP_COMMIT();
    load_kv(1, 1); CP_COMMIT();

    float m0 = -1e30f, m1 = -1e30f, l0 = 0.f, l1 = 0.f;
    float oacc[8][4];
    #pragma unroll
    for (int jj = 0; jj < 8; jj++)
      #pragma unroll
      for (int q = 0; q < 4; q++) oacc[jj][q] = 0.f;

    int s = 0;
    for (int kt = 0; kt < 16; kt++) {
      if (kt + 2 < 16) { load_kv(kt + 2, (s + 2 > 2) ? s - 1 : s + 2); CP_COMMIT(); }
      const int rem = 15 - kt;
      if (rem >= 2) { CP_WAIT(2); } else if (rem == 1) { CP_WAIT(1); } else { CP_WAIT(0); }
      __syncthreads();

      const uint32_t sK = smb + 8192 + s * 16384;
      const uint32_t sV = sK + 8192;

      float sacc[8][4];
      #pragma unroll
      for (int jj = 0; jj < 8; jj++)
        #pragma unroll
        for (int q = 0; q < 4; q++) sacc[jj][q] = 0.f;

      #pragma unroll
      for (int kc = 0; kc < 4; kc++) {
        uint32_t q4[4];
        ldsm4(q4, smb + swz128(warp * 16 + la_row, kc * 2 + la_c));
        #pragma unroll
        for (int n16 = 0; n16 < 4; n16++) {
          uint32_t k4[4];
          ldsm4(k4, sK + swz128(n16 * 16 + lb_row, kc * 2 + lb_c));
          mma16816(sacc[2 * n16],     q4, k4);
          mma16816(sacc[2 * n16 + 1], q4, k4 + 2);
        }
      }

      const float* mrow = mask2 + b * 1024 + kt * 64;
      float mx0 = -1e30f, mx1 = -1e30f;
      #pragma unroll
      for (int jj = 0; jj < 8; jj++) {
        const float2 mv = *(const float2*)(mrow + jj * 8 + 2 * tq);
        sacc[jj][0] += mv.x;
        sacc[jj][1] += mv.y;
        sacc[jj][2] += mv.x;
        sacc[jj][3] += mv.y;
        mx0 = fmaxf(mx0, fmaxf(sacc[jj][0], sacc[jj][1]));
        mx1 = fmaxf(mx1, fmaxf(sacc[jj][2], sacc[jj][3]));
      }
      mx0 = fmaxf(mx0, __shfl_xor_sync(0xffffffffu, mx0, 1));
      mx0 = fmaxf(mx0, __shfl_xor_sync(0xffffffffu, mx0, 2));
      mx1 = fmaxf(mx1, __shfl_xor_sync(0xffffffffu, mx1, 1));
      mx1 = fmaxf(mx1, __shfl_xor_sync(0xffffffffu, mx1, 2));
      const float mn0 = fmaxf(m0, mx0), mn1 = fmaxf(m1, mx1);
      const float rs0 = exp2f(m0 - mn0), rs1 = exp2f(m1 - mn1);
      m0 = mn0; m1 = mn1;

      float sum0 = 0.f, sum1 = 0.f;
      uint32_t ph01[8], ph23[8];
      #pragma unroll
      for (int jj = 0; jj < 8; jj++) {
        const float p0 = exp2f(sacc[jj][0] - mn0), p1 = exp2f(sacc[jj][1] - mn0);
        const float p2 = exp2f(sacc[jj][2] - mn1), p3 = exp2f(sacc[jj][3] - mn1);
        sum0 += p0 + p1; sum1 += p2 + p3;
        ph01[jj] = packh(p0, p1);
        ph23[jj] = packh(p2, p3);
        oacc[jj][0] *= rs0; oacc[jj][1] *= rs0;
        oacc[jj][2] *= rs1; oacc[jj][3] *= rs1;
      }
      sum0 += __shfl_xor_sync(0xffffffffu, sum0, 1);
      sum0 += __shfl_xor_sync(0xffffffffu, sum0, 2);
      sum1 += __shfl_xor_sync(0xffffffffu, sum1, 1);
      sum1 += __shfl_xor_sync(0xffffffffu, sum1, 2);
      l0 = l0 * rs0 + sum0;
      l1 = l1 * rs1 + sum1;

      #pragma unroll
      for (int kc = 0; kc < 4; kc++) {
        uint32_t ah[4] = {ph01[2*kc], ph23[2*kc], ph01[2*kc+1], ph23[2*kc+1]};
        #pragma unroll
        for (int n16 = 0; n16 < 4; n16++) {
          uint32_t v4[4];
          ldsm4t(v4, sV + swz128(kc * 16 + lv_row, n16 * 2 + lv_c));
          mma16816(oacc[2 * n16],     ah, v4);
          mma16816(oacc[2 * n16 + 1], ah, v4 + 2);
        }
      }
      __syncthreads();
      s = (s == 2) ? 0 : s + 1;
    }

    const float inv0 = 1.f / l0, inv1 = 1.f / l1;
    const int row0 = b * 1024 + qt * 64 + warp * 16 + g;
    #pragma unroll
    for (int jj = 0; jj < 8; jj++) {
      const int col = h * 64 + (jj >> 1) * 16 + (jj & 1) * 8 + 2 * tq;
      *(uint32_t*)(Ch + (size_t)row0 * Hd + col)       = packh(oacc[jj][0] * inv0, oacc[jj][1] * inv0);
      *(uint32_t*)(Ch + (size_t)(row0 + 8) * Hd + col) = packh(oacc[jj][2] * inv1, oacc[jj][3] * inv1);
    }
  }
}

// ---------------- fused residual + RMSNorm (float4 vectorized) ----------------
template<bool FOUT>
__global__ void __launch_bounds__(256) rms_kernel(
    const float* __restrict__ in, const float* __restrict__ res,
    const float* __restrict__ g, float* __restrict__ out,
    __half* __restrict__ oh) {
  const int row = blockIdx.x, tid = threadIdx.x;
  __shared__ float red[8];
  __shared__ float s_inv;
  const long base = (long)row * Hd;

  float4 v4 = *(const float4*)(in + base + tid * 4);
  const float4 r4 = *(const float4*)(res + base + tid * 4);
  v4.x += r4.x; v4.y += r4.y; v4.z += r4.z; v4.w += r4.w;
  float ss = v4.x * v4.x + v4.y * v4.y + v4.z * v4.z + v4.w * v4.w;

  #pragma unroll
  for (int o = 16; o; o >>= 1) ss += __shfl_xor_sync(0xffffffffu, ss, o);
  if ((tid & 31) == 0) red[tid >> 5] = ss;
  __syncthreads();
  if (tid == 0) {
    float tot = 0.f;
    #pragma unroll
    for (int i = 0; i < 8; i++) tot += red[i];
    s_inv = rsqrtf(tot * (1.0f / (float)Hd) + 1e-6f);
  }
  __syncthreads();
  const float inv = s_inv;
  const float4 g4 = *(const float4*)(g + tid * 4);
  float4 o4;
  o4.x = v4.x * inv * g4.x;
  o4.y = v4.y * inv * g4.y;
  o4.z = v4.z * inv * g4.z;
  o4.w = v4.w * inv * g4.w;
  *(float4*)(out + base + tid * 4) = o4;
  if (FOUT) {
    uint32_t p0 = packh(o4.x, o4.y), p1 = packh(o4.z, o4.w);
    uint2 hh; hh.x = p0; hh.y = p1;
    *(uint2*)(oh + base + tid * 4) = hh;
  }
}

// ---------------- host ----------------
static const int GEMM_SMEM = 98304;   // 3 stages x 32KB
static const int ATTN_SMEM = 57344;   // Q 8KB + 3 x 16KB

extern "C" void kernel_launch(void* const* d_in, const int* in_sizes, int n_in,
                              void* d_out, int out_size) {
  const float* x    = (const float*)d_in[0];
  const float* y    = (const float*)d_in[1];
  const float* mask = (const float*)d_in[2];
  const float* Wq   = (const float*)d_in[3];
  const float* bq   = (const float*)d_in[4];
  const float* Wk   = (const float*)d_in[5];
  const float* bk   = (const float*)d_in[6];
  const float* Wv   = (const float*)d_in[7];
  const float* bv   = (const float*)d_in[8];
  const float* Wo   = (const float*)d_in[9];
  const float* bo   = (const float*)d_in[10];
  const float* g1   = (const float*)d_in[11];
  const float* Wi   = (const float*)d_in[12];
  const float* bi   = (const float*)d_in[13];
  const float* Wo2  = (const float*)d_in[14];
  const float* bo2  = (const float*)d_in[15];
  const float* g2   = (const float*)d_in[16];
  const int*   t    = (const int*)d_in[17];
  float* out = (float*)d_out;

  cudaFuncSetAttribute(gemm_mma_kernel, cudaFuncAttributeMaxDynamicSharedMemorySize, GEMM_SMEM);
  cudaFuncSetAttribute(attn_mma_kernel, cudaFuncAttributeMaxDynamicSharedMemorySize, ATTN_SMEM);

  float *xs, *att, *tmp, *mask2;
  cudaGetSymbolAddress((void**)&xs,    g_xs);
  cudaGetSymbolAddress((void**)&att,   g_att);
  cudaGetSymbolAddress((void**)&tmp,   g_tmp);
  cudaGetSymbolAddress((void**)&mask2, g_mask2);

  __half *xh,*yh,*qh,*kh,*vh,*ch,*ah,*ih;
  cudaGetSymbolAddress((void**)&xh, g_xh);
  cudaGetSymbolAddress((void**)&yh, g_yh);
  cudaGetSymbolAddress((void**)&qh, g_qh);
  cudaGetSymbolAddress((void**)&kh, g_kh);
  cudaGetSymbolAddress((void**)&vh, g_vh);
  cudaGetSymbolAddress((void**)&ch, g_ch);
  cudaGetSymbolAddress((void**)&ah, g_ah);
  cudaGetSymbolAddress((void**)&ih, g_ih);

  __half *wq,*wk,*wv,*wo,*wi,*w2;
  cudaGetSymbolAddress((void**)&wq, g_wq);
  cudaGetSymbolAddress((void**)&wk, g_wk);
  cudaGetSymbolAddress((void**)&wv, g_wv);
  cudaGetSymbolAddress((void**)&wo, g_wo);
  cudaGetSymbolAddress((void**)&wi, g_wi);
  cudaGetSymbolAddress((void**)&w2, g_w2);

  // fused prologue: routing + weight conversion in one launch
  {
    CvtJobs jb;
    const float* Ws[6] = {Wq, Wk, Wv, Wo, Wi, Wo2};
    __half* Ts[6] = {wq, wk, wv, wo, wi, w2};
    int Ks[6] = {Hd, Hd, Hd, Hd, Hd, Id};
    int Ns[6] = {Hd, Hd, Hd, Hd, Id, Hd};
    int cum = 0;
    for (int i = 0; i < 6; i++) {
      jb.W[i] = Ws[i]; jb.T[i] = Ts[i];
      jb.K[i] = Ks[i]; jb.N[i] = Ns[i];
      jb.tilesX[i] = Ns[i] / 32;
      jb.start[i] = cum;
      cum += (Ns[i] / 32) * (Ks[i] / 32);
    }
    prologue_kernel<<<TOK + cum, 256>>>(x, y, mask, t, xs, mask2, xh, yh, jb);
  }

  const float QSCALE = 0.125f * 1.4426950408889634f;

  {
    GemmJob jq = {xh, wq, bq, nullptr, qh, QSCALE, 2, 0};
    GemmJob jk = {yh, wk, bk, nullptr, kh, 1.0f,   2, 0};
    GemmJob jv = {yh, wv, bv, nullptr, vh, 1.0f,   2, 0};
    gemm_mma_kernel<<<dim3(Hd/128, TOK/128, 3), 256, GEMM_SMEM>>>(jq, jk, jv, TOK, Hd, Hd);
  }

  attn_mma_kernel<<<ATTN_GRID, 128, ATTN_SMEM>>>(qh, kh, vh, mask2, ch);

  {
    GemmJob jo = {ch, wo, bo, tmp, nullptr, 1.0f, 0, 0};
    gemm_mma_kernel<<<dim3(Hd/128, TOK/128, 1), 256, GEMM_SMEM>>>(jo, jo, jo, TOK, Hd, Hd);
  }
  rms_kernel<true ><<<TOK, 256>>>(tmp, xs, g1, att, ah);

  {
    GemmJob ji = {ah, wi, bi, nullptr, ih, 1.0f, 2, 1};
    gemm_mma_kernel<<<dim3(Id/128, TOK/128, 1), 256, GEMM_SMEM>>>(ji, ji, ji, TOK, Id, Hd);
  }
  {
    GemmJob j2 = {ih, w2, bo2, tmp, nullptr, 1.0f, 0, 0};
    gemm_mma_kernel<<<dim3(Hd/128, TOK/128, 1), 256, GEMM_SMEM>>>(j2, j2, j2, TOK, Hd, Id);
  }
  rms_kernel<false><<<TOK, 256>>>(tmp, att, g2, out, nullptr);
}